// round 15
// baseline (speedup 1.0000x reference)
#include <cuda_runtime.h>
#include <math.h>

#define HW      256
#define NPX     65536
#define BATCH   8
#define CH      64
#define PART_STRIDE 256

typedef unsigned long long u64;

// ---------------- scratch (static device globals; no allocation APIs) ----------------
__device__ float  g_bufA[BATCH*CH*NPX];     // 128 MiB
__device__ float  g_bufB[BATCH*CH*NPX];     // 128 MiB
__device__ float2 g_prm[8*BATCH*CH];        // per-layer (mean, inv_std)
__device__ float2 g_part[BATCH*CH*PART_STRIDE];
__device__ float  g_losses[169*BATCH];

__device__ __forceinline__ int clampi(int v, int lo, int hi){ return v<lo?lo:(v>hi?hi:v); }

__device__ __forceinline__ float normact(float v, float2 p){
    float t = (v - p.x) * p.y;          // instance norm
    return t >= 0.f ? t : 0.01f * t;    // leaky relu
}

// ---- packed f32x2 helpers (2 independent fp32 FMAs per instruction) ----
__device__ __forceinline__ u64 pack2(float a, float b){
    u64 r; asm("mov.b64 %0, {%1, %2};" : "=l"(r) : "f"(a), "f"(b)); return r;
}
__device__ __forceinline__ u64 fma2(u64 a, u64 b, u64 c){
    u64 d; asm("fma.rn.f32x2 %0, %1, %2, %3;" : "=l"(d) : "l"(a), "l"(b), "l"(c)); return d;
}
__device__ __forceinline__ void unpack2(u64 v, float& lo, float& hi){
    asm("mov.b64 {%0, %1}, %2;" : "=f"(lo), "=f"(hi) : "l"(v));
}

// block reduction of (sum, sumsq); result valid on thread 0
__device__ __forceinline__ float2 blockReduce2(float s, float q, float2* red){
    const unsigned m = 0xffffffffu;
    #pragma unroll
    for (int o = 16; o > 0; o >>= 1){
        s += __shfl_down_sync(m, s, o);
        q += __shfl_down_sync(m, q, o);
    }
    int wid = threadIdx.x >> 5, lid = threadIdx.x & 31;
    int nw  = (blockDim.x + 31) >> 5;
    __syncthreads();                    // protect red reuse across calls
    if (lid == 0) red[wid] = make_float2(s, q);
    __syncthreads();
    float2 r = make_float2(0.f, 0.f);
    if (wid == 0){
        float2 v = (lid < nw) ? red[lid] : make_float2(0.f, 0.f);
        s = v.x; q = v.y;
        #pragma unroll
        for (int o = 4; o > 0; o >>= 1){
            s += __shfl_down_sync(m, s, o);
            q += __shfl_down_sync(m, q, o);
        }
        r = make_float2(s, q);
    }
    return r;
}

// ---------------- dummy launch-index shifter: makes ncu (-s 5) land on conv_main ----------------
__global__ void dummy_k(float* p){ if (threadIdx.x == 0) p[0] = 0.f; }

// ---------------- layer 0: Conv(1 -> 64) + bias, raw output + stats partials ----------------
__global__ void __launch_bounds__(256) conv_first(
    const float* __restrict__ xin, const float* __restrict__ w0,
    const float* __restrict__ b0, float* __restrict__ out, float2* __restrict__ part)
{
    int y  = blockIdx.x, co = blockIdx.y, b = blockIdx.z;
    int x  = threadIdx.x;
    __shared__ float  w[9];
    __shared__ float2 red[8];
    if (x < 9) w[x] = w0[co*9 + x];
    __syncthreads();
    const float* xp = xin + (size_t)b * NPX;
    float acc = __ldg(&b0[co]);
    #pragma unroll
    for (int ky = 0; ky < 3; ky++){
        int iy = clampi(y + ky - 1, 0, 255);
        #pragma unroll
        for (int kx = 0; kx < 3; kx++){
            int ix = clampi(x + kx - 1, 0, 255);
            acc += w[ky*3 + kx] * xp[iy*256 + ix];
        }
    }
    out[((size_t)(b*CH + co)*256 + y)*256 + x] = acc;
    float2 r = blockReduce2(acc, acc*acc, red);
    if (threadIdx.x == 0) part[(size_t)(b*CH + co)*PART_STRIDE + y] = r;
}

// ---------------- stats finalize: mean + rsqrt(var+eps) per (b,c) ----------------
__global__ void __launch_bounds__(256) stats_k(
    const float2* __restrict__ part, int nPart, float2* __restrict__ prm)
{
    int bc = blockIdx.x;
    __shared__ float2 red[8];
    float s = 0.f, q = 0.f;
    for (int i = threadIdx.x; i < nPart; i += blockDim.x){
        float2 v = part[(size_t)bc*PART_STRIDE + i];
        s += v.x; q += v.y;
    }
    float2 r = blockReduce2(s, q, red);
    if (threadIdx.x == 0){
        const float inv_n = 1.0f / 65536.0f;
        float m   = r.x * inv_n;
        float var = r.y * inv_n - m*m;
        prm[bc] = make_float2(m, rsqrtf(var + 1e-5f));
    }
}

// ---------------- main layers: Conv(64 -> 64), f32x2 packed over CIN pairs ----------------
// grid (8 tilesX, 16 tilesY, b*8 + coblk), block 256
// thread: row r = tid>>4 (0..15), 2 px at xb = (tid&15)*2; 8 output channels.
// Tile stored cin-INTERLEAVED: u64 = (v[cin_even], v[cin_odd]) -> values load
// directly as u64 (no splat MOVs); weights packed (w[co][cin0], w[co][cin1]).
// acc[co][px] holds (sum_even_cins, sum_odd_cins); epilogue adds lo+hi.
// 4 cins staged per barrier (2 pair-buffers per set), 12-LDG prefetch.
__global__ void __launch_bounds__(256, 3) conv_main(
    const float* __restrict__ in, const float2* __restrict__ prmIn,
    const float* __restrict__ w, const float* __restrict__ bias,
    float* __restrict__ out, float2* __restrict__ part)
{
    __shared__ u64    s_w2[32*3*8*4];     // 24 KB: [pair][ky][co][4pad] (w_cin0, w_cin1)
    __shared__ u64    s_norm[4][18*36];   // 4 x 5.06 KB: cin-interleaved pair tiles
    __shared__ float2 s_prm[64];
    __shared__ float2 s_red[8];

    int b     = blockIdx.z >> 3;
    int coblk = blockIdx.z & 7;
    int tx = blockIdx.x * 32, ty = blockIdx.y * 16;
    int tid = threadIdx.x;

    // stage weights packed over cin pairs: [pair][ky][co][k(pad 4)]
    for (int e = tid; e < 32*3*8*3; e += 256){
        int k  = e % 3; int t = e / 3;
        int co = t & 7;  t >>= 3;
        int ky = t % 3; int pr = t / 3;
        int co_g = coblk*8 + co;
        float wa = w[((size_t)co_g*64 + pr*2    )*9 + ky*3 + k];
        float wb = w[((size_t)co_g*64 + pr*2 + 1)*9 + ky*3 + k];
        s_w2[((pr*3 + ky)*8 + co)*4 + k] = pack2(wa, wb);
    }
    if (tid < 64) s_prm[tid] = prmIn[b*64 + tid];

    // cin-invariant staging offsets: 18x34 halo (612), packed (dst<<16 | src)
    unsigned off[3];
    int nldr = 0;
    for (int idx = tid; idx < 18*34; idx += 256){
        int ry = idx / 34, rx = idx - ry*34;
        int gy = clampi(ty + ry - 1, 0, 255);
        int gx = clampi(tx + rx - 1, 0, 255);
        off[nldr++] = ((unsigned)(ry*36 + rx) << 16) | (unsigned)(gy*256 + gx);
    }

    const float* inB = in + (size_t)b * 64 * NPX;

    int r  = tid >> 4;          // 0..15
    int xb = (tid & 15) * 2;    // 0..30, even -> 16B-aligned u64 reads

    u64 acc2[8][2];
    #pragma unroll
    for (int co = 0; co < 8; co++){
        u64 bv = pack2(__ldg(&bias[coblk*8 + co]), 0.f);   // bias in even-partial
        acc2[co][0] = bv; acc2[co][1] = bv;
    }

    // prologue: fetch cins 0..3 and stage into buffers 0,1
    float pfA[3], pfB[3], pfC[3], pfD[3];
    #pragma unroll
    for (int i = 0; i < 3; i++){
        if (i < nldr){
            unsigned s = off[i] & 0xFFFFu;
            pfA[i] = inB[s];
            pfB[i] = inB[s + NPX];
            pfC[i] = inB[s + 2*NPX];
            pfD[i] = inB[s + 3*NPX];
        }
    }
    __syncthreads();            // weights + s_prm visible
    {
        float2 p0 = s_prm[0], p1 = s_prm[1], p2 = s_prm[2], p3 = s_prm[3];
        #pragma unroll
        for (int i = 0; i < 3; i++){
            if (i < nldr){
                unsigned d = off[i] >> 16;
                s_norm[0][d] = pack2(normact(pfA[i], p0), normact(pfB[i], p1));
                s_norm[1][d] = pack2(normact(pfC[i], p2), normact(pfD[i], p3));
            }
        }
    }
    __syncthreads();            // set 0 staged

    for (int sp = 0; sp < 16; sp++){
        int c0 = sp*4;
        // prefetch next 4 cins' raw tiles (12 LDGs in flight)
        if (sp + 1 < 16){
            const float* ip = inB + (size_t)(c0 + 4) * NPX;
            #pragma unroll
            for (int i = 0; i < 3; i++){
                if (i < nldr){
                    unsigned s = off[i] & 0xFFFFu;
                    pfA[i] = ip[s];
                    pfB[i] = ip[s + NPX];
                    pfC[i] = ip[s + 2*NPX];
                    pfD[i] = ip[s + 3*NPX];
                }
            }
        }

        int bufbase = (sp & 1) * 2;
        #pragma unroll
        for (int half = 0; half < 2; half++){
            int pr = sp*2 + half;
            const u64* bufp = s_norm[bufbase + half];
            #pragma unroll
            for (int ky = 0; ky < 3; ky++){
                // 4 cin-pair u64 values: 2 aligned LDS.128
                const ulonglong2* vp = (const ulonglong2*)&bufp[(r + ky)*36 + xb];
                ulonglong2 va = vp[0], vb = vp[1];
                u64 v0 = va.x, v1 = va.y, v2 = vb.x, v3 = vb.y;

                const u64* wrow = &s_w2[(pr*3 + ky)*32];
                #pragma unroll
                for (int co = 0; co < 8; co++){
                    ulonglong2 w01 = *(const ulonglong2*)&wrow[co*4];
                    u64 w2 = wrow[co*4 + 2];
                    acc2[co][0] = fma2(v0, w01.x, acc2[co][0]);
                    acc2[co][0] = fma2(v1, w01.y, acc2[co][0]);
                    acc2[co][0] = fma2(v2, w2,    acc2[co][0]);
                    acc2[co][1] = fma2(v1, w01.x, acc2[co][1]);
                    acc2[co][1] = fma2(v2, w01.y, acc2[co][1]);
                    acc2[co][1] = fma2(v3, w2,    acc2[co][1]);
                }
            }
        }

        // stage next 4 cins into the other buffer set, then one barrier
        if (sp + 1 < 16){
            float2 p0 = s_prm[c0+4], p1 = s_prm[c0+5], p2 = s_prm[c0+6], p3 = s_prm[c0+7];
            int nb = ((sp + 1) & 1) * 2;
            #pragma unroll
            for (int i = 0; i < 3; i++){
                if (i < nldr){
                    unsigned d = off[i] >> 16;
                    s_norm[nb    ][d] = pack2(normact(pfA[i], p0), normact(pfB[i], p1));
                    s_norm[nb + 1][d] = pack2(normact(pfC[i], p2), normact(pfD[i], p3));
                }
            }
        }
        __syncthreads();
    }

    int tileIdx = blockIdx.y*8 + blockIdx.x;   // 0..127
    #pragma unroll
    for (int co = 0; co < 8; co++){
        float lo0, hi0, lo1, hi1;
        unpack2(acc2[co][0], lo0, hi0);
        unpack2(acc2[co][1], lo1, hi1);
        float v0 = lo0 + hi0;      // even-cin partial + odd-cin partial
        float v1 = lo1 + hi1;

        int co_g = coblk*8 + co;
        float* op = out + ((size_t)(b*64 + co_g)*256 + (ty + r))*256 + tx + xb;
        *(float2*)op = make_float2(v0, v1);

        float2 rr = blockReduce2(v0 + v1, v0*v0 + v1*v1, s_red);
        if (tid == 0) part[(size_t)(b*64 + co_g)*PART_STRIDE + tileIdx] = rr;
    }
}

// ---------------- projection Conv(64 -> 1) + residual; writes hr to d_out ----------------
__global__ void __launch_bounds__(256) conv_proj(
    const float* __restrict__ in, const float2* __restrict__ prmIn,
    const float* __restrict__ wp, const float* __restrict__ bp,
    const float* __restrict__ xin, float* __restrict__ hr)
{
    __shared__ float s_w[64*9];
    __shared__ float s_in[34*34];
    int b  = blockIdx.z;
    int tx = blockIdx.x * 32, ty = blockIdx.y * 32;
    int tid = threadIdx.x;

    for (int idx = tid; idx < 576; idx += 256) s_w[idx] = wp[idx];

    int srcOff[5];
    int nldr = 0;
    for (int idx = tid; idx < 34*34; idx += 256){
        int ry = idx / 34, rx = idx - ry*34;
        int gy = clampi(ty + ry - 1, 0, 255);
        int gx = clampi(tx + rx - 1, 0, 255);
        srcOff[nldr++] = gy*256 + gx;
    }

    int r  = tid >> 3;
    int xb = (tid & 7) * 4;

    float acc[4];
    float bv = __ldg(bp);
    #pragma unroll
    for (int p = 0; p < 4; p++) acc[p] = bv;

    for (int cin = 0; cin < 64; cin++){
        __syncthreads();
        float2 pm = prmIn[b*64 + cin];
        const float* ip = in + (size_t)(b*64 + cin) * NPX;
        #pragma unroll
        for (int i = 0; i < 5; i++){
            if (i < nldr) s_in[tid + i*256] = normact(ip[srcOff[i]], pm);
        }
        __syncthreads();

        float v[3][6];
        #pragma unroll
        for (int dy = 0; dy < 3; dy++)
            #pragma unroll
            for (int dx = 0; dx < 6; dx++)
                v[dy][dx] = s_in[(r + dy)*34 + xb + dx];

        const float* wq = &s_w[cin*9];
        #pragma unroll
        for (int ky = 0; ky < 3; ky++)
            #pragma unroll
            for (int kx = 0; kx < 3; kx++){
                float wv = wq[ky*3 + kx];
                #pragma unroll
                for (int p = 0; p < 4; p++)
                    acc[p] += v[ky][kx + p] * wv;
            }
    }

    const float* xp = xin + (size_t)b*NPX + (size_t)(ty + r)*256 + tx + xb;
    float*       op = hr  + (size_t)b*NPX + (size_t)(ty + r)*256 + tx + xb;
    #pragma unroll
    for (int p = 0; p < 4; p++) op[p] = acc[p] + xp[p];
}

// ---------------- shift-search loss: losses[s,b] = Var(hr_crop - t_crop) ----------------
__global__ void __launch_bounds__(256) loss_k(
    const float* __restrict__ hr, const float* __restrict__ tgt, float* __restrict__ losses)
{
    int s = blockIdx.x, b = blockIdx.y;
    int oy = s / 13, ox = s - oy*13;
    const float* hp = hr  + (size_t)b * NPX;
    const float* tp = tgt + (size_t)b * NPX;
    __shared__ float2 red[8];
    float S = 0.f, Q = 0.f;
    for (int i = 0; i < 244; i++){
        const float* hrow = hp + (oy + i)*256 + ox;
        const float* trow = tp + (6 + i)*256 + 6;
        for (int j = threadIdx.x; j < 244; j += 256){
            float d = hrow[j] - trow[j];
            S += d; Q += d*d;
        }
    }
    float2 r = blockReduce2(S, Q, red);
    if (threadIdx.x == 0){
        const float invn = 1.0f / (244.0f*244.0f);
        float m = r.x * invn;
        losses[s*8 + b] = r.y * invn - m*m;
    }
}

// ---------------- final: loss = mean_b min_s losses[s,b] ----------------
__global__ void final_k(const float* __restrict__ losses, float* __restrict__ out, int lossIdx)
{
    __shared__ float bm[8];
    int t = threadIdx.x;
    if (t < 8){
        float mn = 3.4e38f;
        for (int s = 0; s < 169; s++){
            float v = losses[s*8 + t];
            mn = fminf(mn, v);
        }
        bm[t] = mn;
    }
    __syncthreads();
    if (t == 0){
        float acc = 0.f;
        #pragma unroll
        for (int b = 0; b < 8; b++) acc += bm[b];
        out[lossIdx] = acc * 0.125f;
    }
}

// ---------------- host launcher ----------------
extern "C" void kernel_launch(void* const* d_in, const int* in_sizes, int n_in,
                              void* d_out, int out_size)
{
    const float* xIn    = (const float*)d_in[0];
    const float* target = (const float*)d_in[1];
    const float* w0     = (const float*)d_in[2];
    const float* b0     = (const float*)d_in[3];
    const float* ws     = (const float*)d_in[4];
    const float* bs     = (const float*)d_in[5];
    const float* wp     = (const float*)d_in[6];
    const float* bp     = (const float*)d_in[7];
    float* out = (float*)d_out;

    float  *bufA, *bufB, *losses;
    float2 *prm, *part;
    cudaGetSymbolAddress((void**)&bufA,   g_bufA);
    cudaGetSymbolAddress((void**)&bufB,   g_bufB);
    cudaGetSymbolAddress((void**)&prm,    g_prm);
    cudaGetSymbolAddress((void**)&part,   g_part);
    cudaGetSymbolAddress((void**)&losses, g_losses);

    // launch-index shifter: with this, ncu's "-s 5 -c 1" captures conv_main (layer 2)
    dummy_k<<<1, 32>>>(losses);

    // layer 0: Conv(1->64) -> bufA, stats -> prm[0]
    conv_first<<<dim3(256, 64, 8), 256>>>(xIn, w0, b0, bufA, part);
    stats_k<<<512, 256>>>(part, 256, prm);

    // layers 1..7: Conv(64->64), fused norm+lrelu on read, f32x2 over cin pairs
    float* cur = bufA;
    float* nxt = bufB;
    for (int i = 0; i < 7; i++){
        conv_main<<<dim3(8, 16, 64), 256>>>(
            cur, prm + (size_t)i*512,
            ws + (size_t)i*64*64*9, bs + (size_t)i*64,
            nxt, part);
        stats_k<<<512, 256>>>(part, 128, prm + (size_t)(i+1)*512);
        float* tmp = cur; cur = nxt; nxt = tmp;
    }

    // projection + residual -> hr in d_out
    conv_proj<<<dim3(8, 8, 8), 256>>>(cur, prm + (size_t)7*512, wp, bp, xIn, out);

    // shift-search loss
    loss_k<<<dim3(169, 8), 256>>>(out, target, losses);
    final_k<<<1, 32>>>(losses, out, out_size - 1);
}

// round 16
// speedup vs baseline: 2.0043x; 2.0043x over previous
#include <cuda_runtime.h>
#include <math.h>

#define HW      256
#define NPX     65536
#define BATCH   8
#define CH      64
#define PART_STRIDE 256

typedef unsigned long long u64;

// ---------------- scratch (static device globals; no allocation APIs) ----------------
__device__ float  g_bufA[BATCH*CH*NPX];     // 128 MiB
__device__ float  g_bufB[BATCH*CH*NPX];     // 128 MiB
__device__ float2 g_prm[8*BATCH*CH];        // per-layer (mean, inv_std)
__device__ float2 g_part[BATCH*CH*PART_STRIDE];
__device__ float  g_losses[169*BATCH];

__device__ __forceinline__ int clampi(int v, int lo, int hi){ return v<lo?lo:(v>hi?hi:v); }

__device__ __forceinline__ float normact(float v, float2 p){
    float t = (v - p.x) * p.y;          // instance norm
    return t >= 0.f ? t : 0.01f * t;    // leaky relu
}

// ---- packed f32x2 helpers (2 independent fp32 FMAs per instruction) ----
__device__ __forceinline__ u64 pack2(float a, float b){
    u64 r; asm("mov.b64 %0, {%1, %2};" : "=l"(r) : "f"(a), "f"(b)); return r;
}
__device__ __forceinline__ u64 fma2(u64 a, u64 b, u64 c){
    u64 d; asm("fma.rn.f32x2 %0, %1, %2, %3;" : "=l"(d) : "l"(a), "l"(b), "l"(c)); return d;
}
__device__ __forceinline__ void unpack2(u64 v, float& lo, float& hi){
    asm("mov.b64 {%0, %1}, %2;" : "=f"(lo), "=f"(hi) : "l"(v));
}

// block reduction of (sum, sumsq); result valid on thread 0
__device__ __forceinline__ float2 blockReduce2(float s, float q, float2* red){
    const unsigned m = 0xffffffffu;
    #pragma unroll
    for (int o = 16; o > 0; o >>= 1){
        s += __shfl_down_sync(m, s, o);
        q += __shfl_down_sync(m, q, o);
    }
    int wid = threadIdx.x >> 5, lid = threadIdx.x & 31;
    int nw  = (blockDim.x + 31) >> 5;
    __syncthreads();                    // protect red reuse across calls
    if (lid == 0) red[wid] = make_float2(s, q);
    __syncthreads();
    float2 r = make_float2(0.f, 0.f);
    if (wid == 0){
        float2 v = (lid < nw) ? red[lid] : make_float2(0.f, 0.f);
        s = v.x; q = v.y;
        #pragma unroll
        for (int o = 4; o > 0; o >>= 1){
            s += __shfl_down_sync(m, s, o);
            q += __shfl_down_sync(m, q, o);
        }
        r = make_float2(s, q);
    }
    return r;
}

// ---------------- dummy launch-index shifter: makes ncu (-s 5) land on conv_main ----------------
__global__ void dummy_k(float* p){ if (threadIdx.x == 0) p[0] = 0.f; }

// ---------------- layer 0: Conv(1 -> 64) + bias, raw output + stats partials ----------------
__global__ void __launch_bounds__(256) conv_first(
    const float* __restrict__ xin, const float* __restrict__ w0,
    const float* __restrict__ b0, float* __restrict__ out, float2* __restrict__ part)
{
    int y  = blockIdx.x, co = blockIdx.y, b = blockIdx.z;
    int x  = threadIdx.x;
    __shared__ float  w[9];
    __shared__ float2 red[8];
    if (x < 9) w[x] = w0[co*9 + x];
    __syncthreads();
    const float* xp = xin + (size_t)b * NPX;
    float acc = __ldg(&b0[co]);
    #pragma unroll
    for (int ky = 0; ky < 3; ky++){
        int iy = clampi(y + ky - 1, 0, 255);
        #pragma unroll
        for (int kx = 0; kx < 3; kx++){
            int ix = clampi(x + kx - 1, 0, 255);
            acc += w[ky*3 + kx] * xp[iy*256 + ix];
        }
    }
    out[((size_t)(b*CH + co)*256 + y)*256 + x] = acc;
    float2 r = blockReduce2(acc, acc*acc, red);
    if (threadIdx.x == 0) part[(size_t)(b*CH + co)*PART_STRIDE + y] = r;
}

// ---------------- stats finalize: mean + rsqrt(var+eps) per (b,c) ----------------
__global__ void __launch_bounds__(256) stats_k(
    const float2* __restrict__ part, int nPart, float2* __restrict__ prm)
{
    int bc = blockIdx.x;
    __shared__ float2 red[8];
    float s = 0.f, q = 0.f;
    for (int i = threadIdx.x; i < nPart; i += blockDim.x){
        float2 v = part[(size_t)bc*PART_STRIDE + i];
        s += v.x; q += v.y;
    }
    float2 r = blockReduce2(s, q, red);
    if (threadIdx.x == 0){
        const float inv_n = 1.0f / 65536.0f;
        float m   = r.x * inv_n;
        float var = r.y * inv_n - m*m;
        prm[bc] = make_float2(m, rsqrtf(var + 1e-5f));
    }
}

// ---------------- main layers: Conv(64 -> 64), f32x2, quad-cin pipelined staging ----------------
// grid (8 tilesX, 8 tilesY, b*8 + coblk), block 256, DYNAMIC smem (~63 KB)
// thread: row r = tid>>3 (0..31), 4 px at xb = (tid&7)*4; 8 co as 4 packed pairs.
// 8 single-cin float buffers in two sets of 4. Super-iteration = 4 cins:
//   prefetch pair -> compute 2 cins -> stage pair -> prefetch pair -> compute
//   2 cins -> stage pair -> ONE __syncthreads.  (16 barriers total vs 32.)
#define CM_W_BYTES   (64*3*4*4*8)          // 24576: weights [cin][ky][cp][4] u64
#define CM_BUF_FL    (34*36)               // 1224 floats per cin buffer
#define CM_NORM_BYTES (8*CM_BUF_FL*4)      // 39168
#define CM_PRM_BYTES (64*8)                // 512
#define CM_SMEM      (CM_W_BYTES + CM_NORM_BYTES + CM_PRM_BYTES + 64)

__global__ void __launch_bounds__(256, 3) conv_main(
    const float* __restrict__ in, const float2* __restrict__ prmIn,
    const float* __restrict__ w, const float* __restrict__ bias,
    float* __restrict__ out, float2* __restrict__ part)
{
    extern __shared__ unsigned char dynsm[];
    u64*    s_w2   = (u64*)dynsm;                                    // 24 KB
    float*  s_norm = (float*)(dynsm + CM_W_BYTES);                   // 8 x 4.78 KB
    float2* s_prm  = (float2*)(dynsm + CM_W_BYTES + CM_NORM_BYTES);  // 512 B
    float2* s_red  = (float2*)(dynsm + CM_W_BYTES + CM_NORM_BYTES + CM_PRM_BYTES);

    int b     = blockIdx.z >> 3;
    int coblk = blockIdx.z & 7;
    int tx = blockIdx.x * 32, ty = blockIdx.y * 32;
    int tid = threadIdx.x;

    // stage weights pre-duplicated as co-pairs, padded layout for LDS.128 reads
    for (int e = tid; e < 64*3*4*3; e += 256){
        int kx = e % 3; int t = e / 3;
        int cp = t & 3;  t >>= 2;
        int ky = t % 3; int cin = t / 3;
        int co0 = coblk*8 + cp*2;
        float wa = w[((size_t)co0*64 + cin)*9 + ky*3 + kx];
        float wb = w[((size_t)(co0+1)*64 + cin)*9 + ky*3 + kx];
        s_w2[((cin*3 + ky)*4 + cp)*4 + kx] = pack2(wa, wb);
    }
    if (tid < 64) s_prm[tid] = prmIn[b*64 + tid];

    // cin-invariant staging offsets, packed (dst<<16 | src) in 5 registers
    unsigned off[5];
    int nldr = 0;
    for (int idx = tid; idx < 34*34; idx += 256){
        int ry = idx / 34, rx = idx - ry*34;
        int gy = clampi(ty + ry - 1, 0, 255);
        int gx = clampi(tx + rx - 1, 0, 255);
        off[nldr++] = ((unsigned)(ry*36 + rx) << 16) | (unsigned)(gy*256 + gx);
    }

    const float* inB = in + (size_t)b * 64 * NPX;

    int r  = tid >> 3;          // 0..31
    int xb = (tid & 7) * 4;     // 0..28, mult of 4 -> float4 aligned

    u64 acc2[4][4];
    #pragma unroll
    for (int cp = 0; cp < 4; cp++){
        u64 bv = pack2(__ldg(&bias[coblk*8 + cp*2]), __ldg(&bias[coblk*8 + cp*2 + 1]));
        #pragma unroll
        for (int p = 0; p < 4; p++) acc2[cp][p] = bv;
    }

    float pfA[5], pfB[5];

#define PREFETCH_PAIR(cA, cB) {                                         \
    const float* ipA = inB + (size_t)(cA) * NPX;                        \
    const float* ipB = inB + (size_t)(cB) * NPX;                        \
    _Pragma("unroll")                                                   \
    for (int i = 0; i < 5; i++){                                        \
        if (i < nldr){                                                  \
            unsigned s = off[i] & 0xFFFFu;                              \
            pfA[i] = ipA[s]; pfB[i] = ipB[s];                           \
        }                                                               \
    }                                                                   \
}

#define STAGE_PAIR(d0, d1, pA, pB) {                                    \
    float2 q0 = s_prm[pA], q1 = s_prm[pB];                              \
    float* nb0 = s_norm + (d0)*CM_BUF_FL;                               \
    float* nb1 = s_norm + (d1)*CM_BUF_FL;                               \
    _Pragma("unroll")                                                   \
    for (int i = 0; i < 5; i++){                                        \
        if (i < nldr){                                                  \
            unsigned d = off[i] >> 16;                                  \
            nb0[d] = normact(pfA[i], q0);                               \
            nb1[d] = normact(pfB[i], q1);                               \
        }                                                               \
    }                                                                   \
}

#define COMPUTE_CIN(bufIdx, cinIdx) {                                   \
    const float* bufp = s_norm + (bufIdx)*CM_BUF_FL;                    \
    _Pragma("unroll")                                                   \
    for (int ky = 0; ky < 3; ky++){                                     \
        const float* rowp = &bufp[(r + ky)*36 + xb];                    \
        float4 fa = *(const float4*)rowp;                               \
        float2 fb = *(const float2*)(rowp + 4);                         \
        u64 vr[6];                                                      \
        vr[0] = pack2(fa.x, fa.x); vr[1] = pack2(fa.y, fa.y);           \
        vr[2] = pack2(fa.z, fa.z); vr[3] = pack2(fa.w, fa.w);           \
        vr[4] = pack2(fb.x, fb.x); vr[5] = pack2(fb.y, fb.y);           \
        const u64* wrow = &s_w2[((cinIdx)*3 + ky)*16];                  \
        _Pragma("unroll")                                               \
        for (int cp = 0; cp < 4; cp++){                                 \
            ulonglong2 w01 = *(const ulonglong2*)&wrow[cp*4];           \
            u64 w2v = wrow[cp*4 + 2];                                   \
            _Pragma("unroll")                                           \
            for (int p = 0; p < 4; p++){                                \
                acc2[cp][p] = fma2(vr[p],     w01.x, acc2[cp][p]);      \
                acc2[cp][p] = fma2(vr[p + 1], w01.y, acc2[cp][p]);      \
                acc2[cp][p] = fma2(vr[p + 2], w2v,   acc2[cp][p]);      \
            }                                                           \
        }                                                               \
    }                                                                   \
}

    // prologue: stage cins 0..3 into buffers 0..3
    PREFETCH_PAIR(0, 1);
    __syncthreads();            // weights + s_prm visible
    STAGE_PAIR(0, 1, 0, 1);
    PREFETCH_PAIR(2, 3);
    STAGE_PAIR(2, 3, 2, 3);
    __syncthreads();            // set 0 (buffers 0..3) staged

    for (int sp = 0; sp < 16; sp++){
        int c0   = sp*4;
        int curb = (sp & 1) * 4;
        int nxtb = ((sp + 1) & 1) * 4;

        if (sp < 15) PREFETCH_PAIR(c0 + 4, c0 + 5);
        COMPUTE_CIN(curb + 0, c0 + 0);
        COMPUTE_CIN(curb + 1, c0 + 1);
        if (sp < 15) STAGE_PAIR(nxtb + 0, nxtb + 1, c0 + 4, c0 + 5);

        if (sp < 15) PREFETCH_PAIR(c0 + 6, c0 + 7);
        COMPUTE_CIN(curb + 2, c0 + 2);
        COMPUTE_CIN(curb + 3, c0 + 3);
        if (sp < 15) STAGE_PAIR(nxtb + 2, nxtb + 3, c0 + 6, c0 + 7);

        __syncthreads();        // one barrier per 4 cins
    }

    int tileIdx = blockIdx.y*8 + blockIdx.x;   // 0..63
    #pragma unroll
    for (int cp = 0; cp < 4; cp++){
        float lo[4], hi[4];
        #pragma unroll
        for (int p = 0; p < 4; p++) unpack2(acc2[cp][p], lo[p], hi[p]);

        int co0 = coblk*8 + cp*2;
        float* op0 = out + ((size_t)(b*64 + co0  )*256 + (ty + r))*256 + tx + xb;
        float* op1 = out + ((size_t)(b*64 + co0+1)*256 + (ty + r))*256 + tx + xb;
        #pragma unroll
        for (int p = 0; p < 4; p++){ op0[p] = lo[p]; op1[p] = hi[p]; }

        float s0=0.f,q0=0.f,s1=0.f,q1=0.f;
        #pragma unroll
        for (int p = 0; p < 4; p++){
            s0 += lo[p]; q0 += lo[p]*lo[p];
            s1 += hi[p]; q1 += hi[p]*hi[p];
        }
        float2 r0 = blockReduce2(s0, q0, s_red);
        if (tid == 0) part[(size_t)(b*64 + co0)*PART_STRIDE + tileIdx] = r0;
        float2 r1 = blockReduce2(s1, q1, s_red);
        if (tid == 0) part[(size_t)(b*64 + co0 + 1)*PART_STRIDE + tileIdx] = r1;
    }
}

// ---------------- projection Conv(64 -> 1) + residual; writes hr to d_out ----------------
__global__ void __launch_bounds__(256) conv_proj(
    const float* __restrict__ in, const float2* __restrict__ prmIn,
    const float* __restrict__ wp, const float* __restrict__ bp,
    const float* __restrict__ xin, float* __restrict__ hr)
{
    __shared__ float s_w[64*9];
    __shared__ float s_in[34*34];
    int b  = blockIdx.z;
    int tx = blockIdx.x * 32, ty = blockIdx.y * 32;
    int tid = threadIdx.x;

    for (int idx = tid; idx < 576; idx += 256) s_w[idx] = wp[idx];

    int srcOff[5];
    int nldr = 0;
    for (int idx = tid; idx < 34*34; idx += 256){
        int ry = idx / 34, rx = idx - ry*34;
        int gy = clampi(ty + ry - 1, 0, 255);
        int gx = clampi(tx + rx - 1, 0, 255);
        srcOff[nldr++] = gy*256 + gx;
    }

    int r  = tid >> 3;
    int xb = (tid & 7) * 4;

    float acc[4];
    float bv = __ldg(bp);
    #pragma unroll
    for (int p = 0; p < 4; p++) acc[p] = bv;

    for (int cin = 0; cin < 64; cin++){
        __syncthreads();
        float2 pm = prmIn[b*64 + cin];
        const float* ip = in + (size_t)(b*64 + cin) * NPX;
        #pragma unroll
        for (int i = 0; i < 5; i++){
            if (i < nldr) s_in[tid + i*256] = normact(ip[srcOff[i]], pm);
        }
        __syncthreads();

        float v[3][6];
        #pragma unroll
        for (int dy = 0; dy < 3; dy++)
            #pragma unroll
            for (int dx = 0; dx < 6; dx++)
                v[dy][dx] = s_in[(r + dy)*34 + xb + dx];

        const float* wq = &s_w[cin*9];
        #pragma unroll
        for (int ky = 0; ky < 3; ky++)
            #pragma unroll
            for (int kx = 0; kx < 3; kx++){
                float wv = wq[ky*3 + kx];
                #pragma unroll
                for (int p = 0; p < 4; p++)
                    acc[p] += v[ky][kx + p] * wv;
            }
    }

    const float* xp = xin + (size_t)b*NPX + (size_t)(ty + r)*256 + tx + xb;
    float*       op = hr  + (size_t)b*NPX + (size_t)(ty + r)*256 + tx + xb;
    #pragma unroll
    for (int p = 0; p < 4; p++) op[p] = acc[p] + xp[p];
}

// ---------------- shift-search loss: losses[s,b] = Var(hr_crop - t_crop) ----------------
__global__ void __launch_bounds__(256) loss_k(
    const float* __restrict__ hr, const float* __restrict__ tgt, float* __restrict__ losses)
{
    int s = blockIdx.x, b = blockIdx.y;
    int oy = s / 13, ox = s - oy*13;
    const float* hp = hr  + (size_t)b * NPX;
    const float* tp = tgt + (size_t)b * NPX;
    __shared__ float2 red[8];
    float S = 0.f, Q = 0.f;
    for (int i = 0; i < 244; i++){
        const float* hrow = hp + (oy + i)*256 + ox;
        const float* trow = tp + (6 + i)*256 + 6;
        for (int j = threadIdx.x; j < 244; j += 256){
            float d = hrow[j] - trow[j];
            S += d; Q += d*d;
        }
    }
    float2 r = blockReduce2(S, Q, red);
    if (threadIdx.x == 0){
        const float invn = 1.0f / (244.0f*244.0f);
        float m = r.x * invn;
        losses[s*8 + b] = r.y * invn - m*m;
    }
}

// ---------------- final: loss = mean_b min_s losses[s,b] ----------------
__global__ void final_k(const float* __restrict__ losses, float* __restrict__ out, int lossIdx)
{
    __shared__ float bm[8];
    int t = threadIdx.x;
    if (t < 8){
        float mn = 3.4e38f;
        for (int s = 0; s < 169; s++){
            float v = losses[s*8 + t];
            mn = fminf(mn, v);
        }
        bm[t] = mn;
    }
    __syncthreads();
    if (t == 0){
        float acc = 0.f;
        #pragma unroll
        for (int b = 0; b < 8; b++) acc += bm[b];
        out[lossIdx] = acc * 0.125f;
    }
}

// ---------------- host launcher ----------------
extern "C" void kernel_launch(void* const* d_in, const int* in_sizes, int n_in,
                              void* d_out, int out_size)
{
    const float* xIn    = (const float*)d_in[0];
    const float* target = (const float*)d_in[1];
    const float* w0     = (const float*)d_in[2];
    const float* b0     = (const float*)d_in[3];
    const float* ws     = (const float*)d_in[4];
    const float* bs     = (const float*)d_in[5];
    const float* wp     = (const float*)d_in[6];
    const float* bp     = (const float*)d_in[7];
    float* out = (float*)d_out;

    float  *bufA, *bufB, *losses;
    float2 *prm, *part;
    cudaGetSymbolAddress((void**)&bufA,   g_bufA);
    cudaGetSymbolAddress((void**)&bufB,   g_bufB);
    cudaGetSymbolAddress((void**)&prm,    g_prm);
    cudaGetSymbolAddress((void**)&part,   g_part);
    cudaGetSymbolAddress((void**)&losses, g_losses);

    // allow ~63 KB dynamic smem for conv_main (attribute set, not an allocation)
    cudaFuncSetAttribute(conv_main, cudaFuncAttributeMaxDynamicSharedMemorySize, CM_SMEM);

    // launch-index shifter: with this, ncu's "-s 5 -c 1" captures conv_main (layer 2)
    dummy_k<<<1, 32>>>(losses);

    // layer 0: Conv(1->64) -> bufA, stats -> prm[0]
    conv_first<<<dim3(256, 64, 8), 256>>>(xIn, w0, b0, bufA, part);
    stats_k<<<512, 256>>>(part, 256, prm);

    // layers 1..7: Conv(64->64), fused norm+lrelu on read, f32x2, quad-cin pipeline
    float* cur = bufA;
    float* nxt = bufB;
    for (int i = 0; i < 7; i++){
        conv_main<<<dim3(8, 8, 64), 256, CM_SMEM>>>(
            cur, prm + (size_t)i*512,
            ws + (size_t)i*64*64*9, bs + (size_t)i*64,
            nxt, part);
        stats_k<<<512, 256>>>(part, 64, prm + (size_t)(i+1)*512);
        float* tmp = cur; cur = nxt; nxt = tmp;
    }

    // projection + residual -> hr in d_out
    conv_proj<<<dim3(8, 8, 8), 256>>>(cur, prm + (size_t)7*512, wp, bp, xIn, out);

    // shift-search loss
    loss_k<<<dim3(169, 8), 256>>>(out, target, losses);
    final_k<<<1, 32>>>(losses, out, out_size - 1);
}